// round 3
// baseline (speedup 1.0000x reference)
#include <cuda_runtime.h>
#include <math.h>

#define NPTS   2048
#define NGRID  32768   // 32^3
#define NB     8
#define CD     7       // cells per axis
#define NCELL  343     // 7^3
#define SCAN_N 512     // next pow2 >= NCELL
#define TWO_PI_F 6.283185307179586f
#define HCELL   (TWO_PI_F / 7.0f)
#define INV_HCELL (7.0f / TWO_PI_F)
#define EPSB    0.0009765625f     // 2^-10 positivity bias for packed keys
#define KEYMASK 0xFFFFF000u       // keep sign+exp+11 mantissa bits; low 12 = payload
#define FLAGBIT 0x800u            // payload bit 11: entry is a sorted-global index

// Scratch (device globals; no allocations allowed)
__device__ float4 d_pts[2][NPTS];           // sorted-by-cell: (-2x,-2y,-2z, |c|^2)
__device__ int    d_gidx[2][NPTS];          // sorted pos -> original point index
__device__ int    d_cellStart[2][NCELL + 1];
__device__ float  g_flows[2 * NGRID * 3];   // interpolated grid flows

// lattice index i (0..31), position i*2pi/31, belongs to cell min(6, 7i/31)
__device__ __forceinline__ int axis_start(int c) { return (31 * c + 6) / 7; }  // ceil(31c/7)
__device__ __forceinline__ int axis_count(int c) {
    return ((c == CD - 1) ? 32 : axis_start(c + 1)) - axis_start(c);
}

// ---------------------------------------------------------------------------
// Kernel 1: bin points into 7^3 cells. One 1024-thread block per batch.
// counts -> parallel Hillis-Steele scan -> scatter. Also zeroes out[0].
// ---------------------------------------------------------------------------
__global__ __launch_bounds__(1024)
void bin_kernel(const float* __restrict__ coords, float* __restrict__ out)
{
    __shared__ int cnt[SCAN_N];
    __shared__ int ofs[NCELL];
    const int b   = blockIdx.x;
    const int tid = threadIdx.x;

    for (int i = tid; i < SCAN_N; i += blockDim.x) cnt[i] = 0;
    __syncthreads();

    const float* cb = coords + b * NPTS * 3;
    // cache the two points this thread handles (NPTS/1024 = 2)
    float px[2], py[2], pz[2];
    int   pc[2];
#pragma unroll
    for (int k = 0; k < 2; ++k) {
        int j = tid + k * 1024;
        float x = cb[3 * j], y = cb[3 * j + 1], z = cb[3 * j + 2];
        int cx = min(CD - 1, max(0, (int)(x * INV_HCELL)));
        int cy = min(CD - 1, max(0, (int)(y * INV_HCELL)));
        int cz = min(CD - 1, max(0, (int)(z * INV_HCELL)));
        px[k] = x; py[k] = y; pz[k] = z;
        pc[k] = (cx * CD + cy) * CD + cz;
        atomicAdd(&cnt[pc[k]], 1);
    }
    __syncthreads();

    // inclusive scan over SCAN_N entries (first NCELL meaningful)
    for (int off = 1; off < SCAN_N; off <<= 1) {
        int v = 0;
        if (tid < SCAN_N) {
            v = cnt[tid];
            if (tid >= off) v += cnt[tid - off];
        }
        __syncthreads();
        if (tid < SCAN_N) cnt[tid] = v;
        __syncthreads();
    }

    // exclusive starts
    if (tid <= NCELL) {
        int e = (tid == 0) ? 0 : cnt[tid - 1];
        d_cellStart[b][tid] = e;
        if (tid < NCELL) ofs[tid] = e;
    }
    if (tid == 0 && b == 0) out[0] = 0.0f;
    __syncthreads();

#pragma unroll
    for (int k = 0; k < 2; ++k) {
        int j = tid + k * 1024;
        int pos = atomicAdd(&ofs[pc[k]], 1);
        float x = px[k], y = py[k], z = pz[k];
        d_pts[b][pos]  = make_float4(-2.0f * x, -2.0f * y, -2.0f * z,
                                     x * x + y * y + z * z);
        d_gidx[b][pos] = j;
    }
}

// ---------------------------------------------------------------------------
// Kernel 2: exact 8-NN + IDW per grid query, cell-list accelerated.
// One block per (batch, query-cell). Stages the 3x3x3 cell neighborhood
// into shared; each lane of a warp handles one query of this cell (identical
// candidate list -> no control divergence). Top-8 held as packed uint keys
// with a branchless min/max chain. Per-lane covered-radius proof + rare
// incremental shell expansion guarantees exactness for any input.
// ---------------------------------------------------------------------------
__global__ __launch_bounds__(128)
void knn_cell_kernel(const float* __restrict__ flow,
                     const float* __restrict__ grid_coords)
{
    __shared__ float4 pts_s[NPTS];   // worst case: all points staged
    __shared__ int    sidx_s[NPTS];

    const int b    = blockIdx.x / NCELL;
    const int cell = blockIdx.x % NCELL;
    const int cx = cell / (CD * CD);
    const int cy = (cell / CD) % CD;
    const int cz = cell % CD;

    // --- stage ring-1 box (z-contiguous spans) ---
    const int bx0 = max(cx - 1, 0), bx1 = min(cx + 1, CD - 1);
    const int by0 = max(cy - 1, 0), by1 = min(cy + 1, CD - 1);
    const int bz0 = max(cz - 1, 0), bz1 = min(cz + 1, CD - 1);
    int sN = 0;
    for (int ix = bx0; ix <= bx1; ++ix)
        for (int iy = by0; iy <= by1; ++iy) {
            int c0 = (ix * CD + iy) * CD + bz0;
            int c1 = (ix * CD + iy) * CD + bz1;
            int s0 = d_cellStart[b][c0];
            int s1 = d_cellStart[b][c1 + 1];
            int n  = s1 - s0;
            for (int t = threadIdx.x; t < n; t += blockDim.x) {
                pts_s[sN + t]  = d_pts[b][s0 + t];
                sidx_s[sN + t] = s0 + t;
            }
            sN += n;
        }
    __syncthreads();

    // --- queries of this cell ---
    const int x0 = axis_start(cx), y0 = axis_start(cy), z0 = axis_start(cz);
    const int nx = axis_count(cx), ny = axis_count(cy), nz = axis_count(cz);
    const int nq = nx * ny * nz;
    const int nwarp = blockDim.x >> 5;
    const int wid = threadIdx.x >> 5, lane = threadIdx.x & 31;
    const int nchunk = (nq + 31) >> 5;

    for (int ch = wid; ch < nchunk; ch += nwarp) {
        const int ql = ch * 32 + lane;
        const bool active = ql < nq;
        const int qc = active ? ql : 0;
        const int lz = qc % nz;
        const int t1 = qc / nz;
        const int ly = t1 % ny;
        const int lx = t1 / ny;
        const int ix = x0 + lx, iy = y0 + ly, iz = z0 + lz;
        const int m = ((ix * 32) + iy) * 32 + iz;   // meshgrid 'ij' flattening

        const float* g = grid_coords + ((size_t)b * NGRID + (size_t)m) * 3;
        const float gx = g[0], gy = g[1], gz = g[2];
        const float g2 = gx * gx + gy * gy + gz * gz;
        const float G  = g2 + EPSB;   // d2key = |g-c|^2 + EPSB > 0 always

        unsigned bd[NB];
#pragma unroll
        for (int k = 0; k < NB; ++k) bd[k] = 0x7F000000u;  // huge finite sentinel

        // branchless always-insert scan over staged candidates
#pragma unroll 4
        for (int j = 0; j < sN; ++j) {
            float4 p = pts_s[j];
            float d2 = fmaf(gx, p.x, fmaf(gy, p.y, fmaf(gz, p.z, p.w))) + G;
            unsigned key = (__float_as_uint(d2) & KEYMASK) | (unsigned)j;
#pragma unroll
            for (int k = 0; k < NB; ++k) {
                unsigned lo = min(bd[k], key);
                key = max(bd[k], key);
                bd[k] = lo;
            }
        }

        // --- exactness proof + rare incremental shell expansion ---
        int r = 1;
        while (true) {
            float cov = 1e30f;
            if (cx - r > 0)      cov = fminf(cov, gx - (float)(cx - r) * HCELL);
            if (cx + r < CD - 1) cov = fminf(cov, (float)(cx + r + 1) * HCELL - gx);
            if (cy - r > 0)      cov = fminf(cov, gy - (float)(cy - r) * HCELL);
            if (cy + r < CD - 1) cov = fminf(cov, (float)(cy + r + 1) * HCELL - gy);
            if (cz - r > 0)      cov = fminf(cov, gz - (float)(cz - r) * HCELL);
            if (cz + r < CD - 1) cov = fminf(cov, (float)(cz + r + 1) * HCELL - gz);
            float d2_8 = __uint_as_float(bd[NB - 1] & KEYMASK);
            bool ok = (!active) || (r >= CD - 1) ||
                      (d2_8 * 1.001f + 0.01f <= cov * cov);
            if (__all_sync(0xFFFFFFFFu, ok)) break;

            ++r;  // scan shell at Chebyshev distance r (no duplicates)
            int ex0 = max(cx - r, 0), ex1 = min(cx + r, CD - 1);
            int ey0 = max(cy - r, 0), ey1 = min(cy + r, CD - 1);
            int ez0 = max(cz - r, 0), ez1 = min(cz + r, CD - 1);
            for (int jx = ex0; jx <= ex1; ++jx)
                for (int jy = ey0; jy <= ey1; ++jy)
                    for (int jz = ez0; jz <= ez1; ++jz) {
                        int chb = max(abs(jx - cx), max(abs(jy - cy), abs(jz - cz)));
                        if (chb != r) continue;
                        int cid = (jx * CD + jy) * CD + jz;
                        int s0 = d_cellStart[b][cid];
                        int s1 = d_cellStart[b][cid + 1];
                        for (int s = s0; s < s1; ++s) {
                            float4 p = d_pts[b][s];
                            float d2 = fmaf(gx, p.x, fmaf(gy, p.y, fmaf(gz, p.z, p.w))) + G;
                            unsigned key = (__float_as_uint(d2) & KEYMASK) |
                                           FLAGBIT | (unsigned)s;
#pragma unroll
                            for (int k = 0; k < NB; ++k) {
                                unsigned lo = min(bd[k], key);
                                key = max(bd[k], key);
                                bd[k] = lo;
                            }
                        }
                    }
        }

        // --- IDW weights on exact recomputed distances ---
        if (active) {
            const float* fb = flow + b * NPTS * 3;
            float wsum = 0.f, fxa = 0.f, fya = 0.f, fza = 0.f;
#pragma unroll
            for (int k = 0; k < NB; ++k) {
                unsigned e = bd[k] & 0xFFFu;
                int s = (e & FLAGBIT) ? (int)(e & 0x7FFu) : sidx_s[e];
                float4 p = d_pts[b][s];
                float d2f = fmaf(gx, p.x, fmaf(gy, p.y, fmaf(gz, p.z, p.w))) + g2;
                d2f = fmaxf(d2f, 0.0f);
                float rsq = __frsqrt_rn(fmaxf(d2f, 1e-30f));
                float dist = d2f * rsq;                 // sqrt(d2f)
                float tt = dist + 1e-8f;
                float w = __fdividef(1.0f, tt * tt);
                wsum += w;
                int gi = d_gidx[b][s];
                fxa = fmaf(w, fb[3 * gi + 0], fxa);
                fya = fmaf(w, fb[3 * gi + 1], fya);
                fza = fmaf(w, fb[3 * gi + 2], fza);
            }
            float inv = __fdividef(1.0f, wsum);
            float* o = g_flows + ((size_t)b * NGRID + (size_t)m) * 3;
            o[0] = fxa * inv;
            o[1] = fya * inv;
            o[2] = fza * inv;
        }
    }
}

// ---------------------------------------------------------------------------
// Kernel 3: divergence (torch.gradient semantics, h = 2pi/32) + mean(|div|).
// ---------------------------------------------------------------------------
__device__ __forceinline__ float gf_at(const float* base, int x, int y, int z, int c)
{
    return base[((((x << 5) + y) << 5) + z) * 3 + c];
}

__global__ __launch_bounds__(256)
void div_kernel(float* __restrict__ out)
{
    const float H     = TWO_PI_F / 32.0f;
    const float invH  = 1.0f / H;
    const float inv2H = 0.5f / H;

    int t = blockIdx.x * 256 + threadIdx.x;   // 0 .. 65535
    int b = t >> 15;
    int m = t & (NGRID - 1);
    int iz = m & 31;
    int iy = (m >> 5) & 31;
    int ix = m >> 10;

    const float* base = g_flows + (size_t)b * NGRID * 3;

    float dx, dy, dz;
    if (ix == 0)       dx = (gf_at(base, 1, iy, iz, 0)      - gf_at(base, 0, iy, iz, 0))      * invH;
    else if (ix == 31) dx = (gf_at(base, 31, iy, iz, 0)     - gf_at(base, 30, iy, iz, 0))     * invH;
    else               dx = (gf_at(base, ix + 1, iy, iz, 0) - gf_at(base, ix - 1, iy, iz, 0)) * inv2H;

    if (iy == 0)       dy = (gf_at(base, ix, 1, iz, 1)      - gf_at(base, ix, 0, iz, 1))      * invH;
    else if (iy == 31) dy = (gf_at(base, ix, 31, iz, 1)     - gf_at(base, ix, 30, iz, 1))     * invH;
    else               dy = (gf_at(base, ix, iy + 1, iz, 1) - gf_at(base, ix, iy - 1, iz, 1)) * inv2H;

    if (iz == 0)       dz = (gf_at(base, ix, iy, 1, 2)      - gf_at(base, ix, iy, 0, 2))      * invH;
    else if (iz == 31) dz = (gf_at(base, ix, iy, 31, 2)     - gf_at(base, ix, iy, 30, 2))     * invH;
    else               dz = (gf_at(base, ix, iy, iz + 1, 2) - gf_at(base, ix, iy, iz - 1, 2)) * inv2H;

    float v = fabsf(dx + dy + dz);

    __shared__ float sdata[256];
    sdata[threadIdx.x] = v;
    __syncthreads();
#pragma unroll
    for (int s = 128; s >= 32; s >>= 1) {
        if (threadIdx.x < s) sdata[threadIdx.x] += sdata[threadIdx.x + s];
        __syncthreads();
    }
    if (threadIdx.x < 32) {
        float r = sdata[threadIdx.x];
#pragma unroll
        for (int off = 16; off > 0; off >>= 1)
            r += __shfl_down_sync(0xFFFFFFFFu, r, off);
        if (threadIdx.x == 0)
            atomicAdd(out, r * (1.0f / 65536.0f));
    }
}

// ---------------------------------------------------------------------------
// Launch
// ---------------------------------------------------------------------------
extern "C" void kernel_launch(void* const* d_in, const int* in_sizes, int n_in,
                              void* d_out, int out_size)
{
    const float* flow        = (const float*)d_in[0];   // (2, 2048, 3)
    const float* coords      = (const float*)d_in[1];   // (2, 2048, 3)
    const float* grid_coords = (const float*)d_in[2];   // (2, 32768, 3)
    float* out = (float*)d_out;                         // scalar

    bin_kernel<<<2, 1024>>>(coords, out);
    knn_cell_kernel<<<2 * NCELL, 128>>>(flow, grid_coords);
    div_kernel<<<256, 256>>>(out);
}

// round 5
// speedup vs baseline: 1.2420x; 1.2420x over previous
#include <cuda_runtime.h>
#include <math.h>

#define NPTS   2048
#define NGRID  32768   // 32^3
#define NB     8
#define CD     6       // cells per axis
#define NCELL  216     // 6^3
#define TWO_PI_F 6.283185307179586f
#define HCELL   (TWO_PI_F / 6.0f)
#define INV_HCELL (6.0f / TWO_PI_F)
#define EPSB    0.0009765625f     // 2^-10 positivity bias for packed keys
#define KEYMASK 0xFFFFF000u       // sign+exp+11 mantissa bits; low 12 = payload
#define FLAGBIT 0x800u            // payload bit 11: sorted-global index entry
#define SENT    0x7F000000u       // huge finite sentinel key

// Scratch (device globals; no allocations allowed)
__device__ float4 d_pts[2][NPTS];           // sorted-by-cell: (-2x,-2y,-2z, |c|^2)
__device__ int    d_gidx[2][NPTS];          // sorted pos -> original point index
__device__ int    d_cellStart[2][NCELL + 1];
__device__ float  g_flows[2 * NGRID * 3];   // interpolated grid flows

// lattice index i belongs to cell floor(6*i/31); first index of cell c:
__device__ __forceinline__ int axis_start(int c) { return (31 * c + 5) / 6; }
__device__ __forceinline__ int axis_count(int c) {
    return ((c == CD - 1) ? 32 : axis_start(c + 1)) - axis_start(c);
}

// branchless insert of `key` into ascending sorted top-8 array bd[]
__device__ __forceinline__ void ins8(unsigned* bd, unsigned key)
{
#pragma unroll
    for (int k = 0; k < NB; ++k) {
        unsigned lo = min(bd[k], key);
        key = max(bd[k], key);
        bd[k] = lo;
    }
}

// ---------------------------------------------------------------------------
// Kernel 1: bin points into 6^3 cells. One 1024-thread block per batch.
// Count with smem atomics; prefix scan done by warp 0 (7 cells/lane + shfl)
// so the whole kernel has only 3 block barriers. Also zeroes out[0].
// ---------------------------------------------------------------------------
__global__ __launch_bounds__(1024)
void bin_kernel(const float* __restrict__ coords, float* __restrict__ out)
{
    __shared__ int cnt[NCELL];
    __shared__ int ofs[NCELL];
    const int b   = blockIdx.x;
    const int tid = threadIdx.x;

    for (int i = tid; i < NCELL; i += 1024) cnt[i] = 0;
    __syncthreads();

    const float* cb = coords + b * NPTS * 3;
    float px[2], py[2], pz[2];
    int   pc[2];
#pragma unroll
    for (int k = 0; k < 2; ++k) {
        int j = tid + k * 1024;
        float x = cb[3 * j], y = cb[3 * j + 1], z = cb[3 * j + 2];
        int cx = min(CD - 1, max(0, (int)(x * INV_HCELL)));
        int cy = min(CD - 1, max(0, (int)(y * INV_HCELL)));
        int cz = min(CD - 1, max(0, (int)(z * INV_HCELL)));
        px[k] = x; py[k] = y; pz[k] = z;
        pc[k] = (cx * CD + cy) * CD + cz;
        atomicAdd(&cnt[pc[k]], 1);
    }
    if (tid == 0 && b == 0) out[0] = 0.0f;
    __syncthreads();

    // warp 0: exclusive prefix over 216 cells, 7 cells per lane
    if (tid < 32) {
        const int base = tid * 7;
        int v[7];
        int lanesum = 0;
#pragma unroll
        for (int k = 0; k < 7; ++k) {
            int c = base + k;
            v[k] = (c < NCELL) ? cnt[c] : 0;
            lanesum += v[k];
        }
        int ex = lanesum;
#pragma unroll
        for (int off = 1; off < 32; off <<= 1) {
            int n = __shfl_up_sync(0xFFFFFFFFu, ex, off);
            if (tid >= off) ex += n;
        }
        ex -= lanesum;                 // exclusive prefix of this lane's range
        int run = ex;
#pragma unroll
        for (int k = 0; k < 7; ++k) {
            int c = base + k;
            if (c < NCELL) {
                ofs[c] = run;
                d_cellStart[b][c] = run;
                run += v[k];
            }
        }
        if (tid == 31) d_cellStart[b][NCELL] = run;   // = NPTS
    }
    __syncthreads();

#pragma unroll
    for (int k = 0; k < 2; ++k) {
        int j = tid + k * 1024;
        int pos = atomicAdd(&ofs[pc[k]], 1);
        float x = px[k], y = py[k], z = pz[k];
        d_pts[b][pos]  = make_float4(-2.0f * x, -2.0f * y, -2.0f * z,
                                     x * x + y * y + z * z);
        d_gidx[b][pos] = j;
    }
}

// ---------------------------------------------------------------------------
// Kernel 2: exact 8-NN + IDW per grid query, cell-list accelerated.
// One 256-thread block per (batch, query-cell): 8 warps for latency hiding.
// Candidates scanned 2-at-a-time into two independent top-8 chains (2x ILP
// on the serial IMNMX dependency), merged once with the sorted-merge trick.
// Per-lane covered-radius proof + rare shell expansion keeps it exact.
// ---------------------------------------------------------------------------
__global__ __launch_bounds__(256, 3)
void knn_cell_kernel(const float* __restrict__ flow,
                     const float* __restrict__ grid_coords)
{
    __shared__ float4 pts_s[NPTS];   // worst case: all points staged
    __shared__ int    sidx_s[NPTS];

    const int b    = blockIdx.x / NCELL;
    const int cell = blockIdx.x % NCELL;
    const int cx = cell / (CD * CD);
    const int cy = (cell / CD) % CD;
    const int cz = cell % CD;

    // --- stage ring-1 box (z-contiguous spans) ---
    const int bx0 = max(cx - 1, 0), bx1 = min(cx + 1, CD - 1);
    const int by0 = max(cy - 1, 0), by1 = min(cy + 1, CD - 1);
    const int bz0 = max(cz - 1, 0), bz1 = min(cz + 1, CD - 1);
    int sN = 0;
    for (int ix = bx0; ix <= bx1; ++ix)
        for (int iy = by0; iy <= by1; ++iy) {
            int c0 = (ix * CD + iy) * CD + bz0;
            int c1 = (ix * CD + iy) * CD + bz1;
            int s0 = d_cellStart[b][c0];
            int s1 = d_cellStart[b][c1 + 1];
            int n  = s1 - s0;
            for (int t = threadIdx.x; t < n; t += blockDim.x) {
                pts_s[sN + t]  = d_pts[b][s0 + t];
                sidx_s[sN + t] = s0 + t;
            }
            sN += n;
        }
    __syncthreads();

    // --- queries of this cell ---
    const int x0 = axis_start(cx), y0 = axis_start(cy), z0 = axis_start(cz);
    const int nx = axis_count(cx), ny = axis_count(cy), nz = axis_count(cz);
    const int nq = nx * ny * nz;
    const int wid = threadIdx.x >> 5, lane = threadIdx.x & 31;
    const int nchunk = (nq + 31) >> 5;

    for (int ch = wid; ch < nchunk; ch += 8) {
        const int ql = ch * 32 + lane;
        const bool active = ql < nq;
        const int qc = active ? ql : 0;
        const int lz = qc % nz;
        const int t1 = qc / nz;
        const int ly = t1 % ny;
        const int lx = t1 / ny;
        const int ix = x0 + lx, iy = y0 + ly, iz = z0 + lz;
        const int m = ((ix * 32) + iy) * 32 + iz;   // meshgrid 'ij' flattening

        const float* g = grid_coords + ((size_t)b * NGRID + (size_t)m) * 3;
        const float gx = g[0], gy = g[1], gz = g[2];
        const float g2 = gx * gx + gy * gy + gz * gz;
        const float G  = g2 + EPSB;   // keyed d2 = |g-c|^2 + EPSB > 0 always

        unsigned bdA[NB], bdB[NB];
#pragma unroll
        for (int k = 0; k < NB; ++k) { bdA[k] = SENT; bdB[k] = SENT; }

        // dual-chain branchless scan (2 candidates/iter)
        int j = 0;
        for (; j + 1 < sN; j += 2) {
            float4 p0 = pts_s[j];
            float4 p1 = pts_s[j + 1];
            float d0 = fmaf(gx, p0.x, fmaf(gy, p0.y, fmaf(gz, p0.z, p0.w))) + G;
            float d1 = fmaf(gx, p1.x, fmaf(gy, p1.y, fmaf(gz, p1.z, p1.w))) + G;
            unsigned k0 = (__float_as_uint(d0) & KEYMASK) | (unsigned)j;
            unsigned k1 = (__float_as_uint(d1) & KEYMASK) | (unsigned)(j + 1);
            ins8(bdA, k0);
            ins8(bdB, k1);
        }
        if (j < sN) {
            float4 p0 = pts_s[j];
            float d0 = fmaf(gx, p0.x, fmaf(gy, p0.y, fmaf(gz, p0.z, p0.w))) + G;
            ins8(bdA, (__float_as_uint(d0) & KEYMASK) | (unsigned)j);
        }

        // merge: 8 smallest of two sorted-8 lists = elementwise min(A[i], B[7-i])
        unsigned bd[NB];
#pragma unroll
        for (int k = 0; k < NB; ++k) bd[k] = min(bdA[k], bdB[NB - 1 - k]);
        // bd is the correct SET (unsorted)

        // --- exactness proof + rare incremental shell expansion ---
        bool sorted = false;
        int r = 1;
        while (true) {
            float cov = 1e30f;
            if (cx - r > 0)      cov = fminf(cov, gx - (float)(cx - r) * HCELL);
            if (cx + r < CD - 1) cov = fminf(cov, (float)(cx + r + 1) * HCELL - gx);
            if (cy - r > 0)      cov = fminf(cov, gy - (float)(cy - r) * HCELL);
            if (cy + r < CD - 1) cov = fminf(cov, (float)(cy + r + 1) * HCELL - gy);
            if (cz - r > 0)      cov = fminf(cov, gz - (float)(cz - r) * HCELL);
            if (cz + r < CD - 1) cov = fminf(cov, (float)(cz + r + 1) * HCELL - gz);
            unsigned mx = bd[0];
#pragma unroll
            for (int k = 1; k < NB; ++k) mx = max(mx, bd[k]);
            float d2_8 = __uint_as_float(mx & KEYMASK);
            bool ok = (!active) || (r >= CD - 1) ||
                      (d2_8 * 1.001f + 0.01f <= cov * cov);
            if (__all_sync(0xFFFFFFFFu, ok)) break;

            if (!sorted) {            // rebuild ascending order for chain inserts
                unsigned tmp[NB];
#pragma unroll
                for (int k = 0; k < NB; ++k) { tmp[k] = bd[k]; bd[k] = SENT; }
#pragma unroll
                for (int k = 0; k < NB; ++k) ins8(bd, tmp[k]);
                sorted = true;
            }

            ++r;  // scan shell at Chebyshev distance r (no duplicates)
            int ex0 = max(cx - r, 0), ex1 = min(cx + r, CD - 1);
            int ey0 = max(cy - r, 0), ey1 = min(cy + r, CD - 1);
            int ez0 = max(cz - r, 0), ez1 = min(cz + r, CD - 1);
            for (int jx = ex0; jx <= ex1; ++jx)
                for (int jy = ey0; jy <= ey1; ++jy)
                    for (int jz = ez0; jz <= ez1; ++jz) {
                        int chb = max(abs(jx - cx), max(abs(jy - cy), abs(jz - cz)));
                        if (chb != r) continue;
                        int cid = (jx * CD + jy) * CD + jz;
                        int s0 = d_cellStart[b][cid];
                        int s1 = d_cellStart[b][cid + 1];
                        for (int s = s0; s < s1; ++s) {
                            float4 p = d_pts[b][s];
                            float d2 = fmaf(gx, p.x, fmaf(gy, p.y, fmaf(gz, p.z, p.w))) + G;
                            ins8(bd, (__float_as_uint(d2) & KEYMASK) |
                                      FLAGBIT | (unsigned)s);
                        }
                    }
        }

        // --- IDW on exact recomputed distances (bd order irrelevant) ---
        if (active) {
            const float* fb = flow + b * NPTS * 3;
            float wsum = 0.f, fxa = 0.f, fya = 0.f, fza = 0.f;
#pragma unroll
            for (int k = 0; k < NB; ++k) {
                unsigned e = bd[k] & 0xFFFu;
                int s = (e & FLAGBIT) ? (int)(e & 0x7FFu) : sidx_s[e];
                float4 p = d_pts[b][s];
                float d2f = fmaf(gx, p.x, fmaf(gy, p.y, fmaf(gz, p.z, p.w))) + g2;
                d2f = fmaxf(d2f, 0.0f);
                float rsq = __frsqrt_rn(fmaxf(d2f, 1e-30f));
                float dist = d2f * rsq;                 // sqrt(d2f)
                float tt = dist + 1e-8f;
                float w = __fdividef(1.0f, tt * tt);
                wsum += w;
                int gi = d_gidx[b][s];
                fxa = fmaf(w, fb[3 * gi + 0], fxa);
                fya = fmaf(w, fb[3 * gi + 1], fya);
                fza = fmaf(w, fb[3 * gi + 2], fza);
            }
            float inv = __fdividef(1.0f, wsum);
            float* o = g_flows + ((size_t)b * NGRID + (size_t)m) * 3;
            o[0] = fxa * inv;
            o[1] = fya * inv;
            o[2] = fza * inv;
        }
    }
}

// ---------------------------------------------------------------------------
// Kernel 3: divergence (torch.gradient semantics, h = 2pi/32) + mean(|div|).
// ---------------------------------------------------------------------------
__device__ __forceinline__ float gf_at(const float* base, int x, int y, int z, int c)
{
    return base[((((x << 5) + y) << 5) + z) * 3 + c];
}

__global__ __launch_bounds__(256)
void div_kernel(float* __restrict__ out)
{
    const float H     = TWO_PI_F / 32.0f;
    const float invH  = 1.0f / H;
    const float inv2H = 0.5f / H;

    int t = blockIdx.x * 256 + threadIdx.x;   // 0 .. 65535
    int b = t >> 15;
    int m = t & (NGRID - 1);
    int iz = m & 31;
    int iy = (m >> 5) & 31;
    int ix = m >> 10;

    const float* base = g_flows + (size_t)b * NGRID * 3;

    float dx, dy, dz;
    if (ix == 0)       dx = (gf_at(base, 1, iy, iz, 0)      - gf_at(base, 0, iy, iz, 0))      * invH;
    else if (ix == 31) dx = (gf_at(base, 31, iy, iz, 0)     - gf_at(base, 30, iy, iz, 0))     * invH;
    else               dx = (gf_at(base, ix + 1, iy, iz, 0) - gf_at(base, ix - 1, iy, iz, 0)) * inv2H;

    if (iy == 0)       dy = (gf_at(base, ix, 1, iz, 1)      - gf_at(base, ix, 0, iz, 1))      * invH;
    else if (iy == 31) dy = (gf_at(base, ix, 31, iz, 1)     - gf_at(base, ix, 30, iz, 1))     * invH;
    else               dy = (gf_at(base, ix, iy + 1, iz, 1) - gf_at(base, ix, iy - 1, iz, 1)) * inv2H;

    if (iz == 0)       dz = (gf_at(base, ix, iy, 1, 2)      - gf_at(base, ix, iy, 0, 2))      * invH;
    else if (iz == 31) dz = (gf_at(base, ix, iy, 31, 2)     - gf_at(base, ix, iy, 30, 2))     * invH;
    else               dz = (gf_at(base, ix, iy, iz + 1, 2) - gf_at(base, ix, iy, iz - 1, 2)) * inv2H;

    float v = fabsf(dx + dy + dz);

    __shared__ float sdata[256];
    sdata[threadIdx.x] = v;
    __syncthreads();
#pragma unroll
    for (int s = 128; s >= 32; s >>= 1) {
        if (threadIdx.x < s) sdata[threadIdx.x] += sdata[threadIdx.x + s];
        __syncthreads();
    }
    if (threadIdx.x < 32) {
        float r = sdata[threadIdx.x];
#pragma unroll
        for (int off = 16; off > 0; off >>= 1)
            r += __shfl_down_sync(0xFFFFFFFFu, r, off);
        if (threadIdx.x == 0)
            atomicAdd(out, r * (1.0f / 65536.0f));
    }
}

// ---------------------------------------------------------------------------
// Launch
// ---------------------------------------------------------------------------
extern "C" void kernel_launch(void* const* d_in, const int* in_sizes, int n_in,
                              void* d_out, int out_size)
{
    const float* flow        = (const float*)d_in[0];   // (2, 2048, 3)
    const float* coords      = (const float*)d_in[1];   // (2, 2048, 3)
    const float* grid_coords = (const float*)d_in[2];   // (2, 32768, 3)
    float* out = (float*)d_out;                         // scalar

    bin_kernel<<<2, 1024>>>(coords, out);
    knn_cell_kernel<<<2 * NCELL, 256>>>(flow, grid_coords);
    div_kernel<<<256, 256>>>(out);
}